// round 2
// baseline (speedup 1.0000x reference)
#include <cuda_runtime.h>
#include <cstdint>
#include <cstddef>

// Problem constants
#define BB 64
#define TT 512
#define II 1024
#define HH 1024

// ---------------- scratch (device globals; no cudaMalloc allowed) ----------------
__device__ float g_xw[(size_t)BB * TT * HH];      // 128 MiB: xw = x@W^T + bW
__device__ float g_state[2][(size_t)BB * HH];     // ping-pong recurrent state
__device__ unsigned g_bar_count;
__device__ unsigned g_bar_gen;

// ---------------- grid-wide software barrier (all CTAs resident) ----------------
__device__ __forceinline__ void grid_sync(unsigned nctas) {
    __syncthreads();
    if (threadIdx.x == 0) {
        unsigned g = *((volatile unsigned*)&g_bar_gen);
        __threadfence();
        unsigned a = atomicAdd(&g_bar_count, 1u);
        if (a == nctas - 1u) {
            g_bar_count = 0u;
            __threadfence();
            *((volatile unsigned*)&g_bar_gen) = g + 1u;
        } else {
            while (*((volatile unsigned*)&g_bar_gen) == g) { __nanosleep(64); }
        }
        __threadfence();
    }
    __syncthreads();
}

// ---------------- fast accurate tanh (MUFU EX2 + RCP, ~1e-7 rel err) ----------------
__device__ __forceinline__ float fast_tanh(float x) {
    float ax = fabsf(x);
    float e  = __expf(-2.0f * ax);
    float r  = __fdividef(1.0f - e, 1.0f + e);
    return copysignf(r, x);
}

// =====================================================================
// Kernel 1: xw[m][n] = sum_k x[m][k] * W[n][k] + bW[n]
// M = B*T = 32768, N = H = 1024, K = I = 1024
// 64x64 tile, BK=16, 256 threads, 4x4 microtile.
// =====================================================================
#define BM 64
#define BN 64
#define BK 16

__global__ __launch_bounds__(256) void gemm1_kernel(
    const float* __restrict__ x, const float* __restrict__ W,
    const float* __restrict__ bW)
{
    __shared__ float As[BK][BM];   // [k][m]
    __shared__ float Bs[BK][BN];   // [k][n]

    const int tid = threadIdx.x;
    const int tx = tid & 15;         // 0..15 -> n micro
    const int ty = tid >> 4;         // 0..15 -> m micro
    const int m_blk = blockIdx.y * BM;
    const int n_blk = blockIdx.x * BN;

    const int lr  = tid >> 2;        // 0..63  row within tile for loads
    const int lkq = tid & 3;         // 0..3   k-quad for loads

    float acc[4][4];
#pragma unroll
    for (int i = 0; i < 4; ++i)
#pragma unroll
        for (int j = 0; j < 4; ++j) acc[i][j] = 0.0f;

    for (int kk = 0; kk < II; kk += BK) {
        // load A tile (64 rows x 16 k) and W tile (64 rows x 16 k), transpose into smem
        float4 a4 = *(const float4*)&x[(size_t)(m_blk + lr) * II + kk + lkq * 4];
        float4 b4 = *(const float4*)&W[(size_t)(n_blk + lr) * II + kk + lkq * 4];
        __syncthreads();
        As[lkq * 4 + 0][lr] = a4.x; As[lkq * 4 + 1][lr] = a4.y;
        As[lkq * 4 + 2][lr] = a4.z; As[lkq * 4 + 3][lr] = a4.w;
        Bs[lkq * 4 + 0][lr] = b4.x; Bs[lkq * 4 + 1][lr] = b4.y;
        Bs[lkq * 4 + 2][lr] = b4.z; Bs[lkq * 4 + 3][lr] = b4.w;
        __syncthreads();
#pragma unroll
        for (int k = 0; k < BK; ++k) {
            float4 av = *(const float4*)&As[k][ty * 4];
            float4 bv = *(const float4*)&Bs[k][tx * 4];
            acc[0][0] = fmaf(av.x, bv.x, acc[0][0]);
            acc[0][1] = fmaf(av.x, bv.y, acc[0][1]);
            acc[0][2] = fmaf(av.x, bv.z, acc[0][2]);
            acc[0][3] = fmaf(av.x, bv.w, acc[0][3]);
            acc[1][0] = fmaf(av.y, bv.x, acc[1][0]);
            acc[1][1] = fmaf(av.y, bv.y, acc[1][1]);
            acc[1][2] = fmaf(av.y, bv.z, acc[1][2]);
            acc[1][3] = fmaf(av.y, bv.w, acc[1][3]);
            acc[2][0] = fmaf(av.z, bv.x, acc[2][0]);
            acc[2][1] = fmaf(av.z, bv.y, acc[2][1]);
            acc[2][2] = fmaf(av.z, bv.z, acc[2][2]);
            acc[2][3] = fmaf(av.z, bv.w, acc[2][3]);
            acc[3][0] = fmaf(av.w, bv.x, acc[3][0]);
            acc[3][1] = fmaf(av.w, bv.y, acc[3][1]);
            acc[3][2] = fmaf(av.w, bv.z, acc[3][2]);
            acc[3][3] = fmaf(av.w, bv.w, acc[3][3]);
        }
    }

    float4 bw4 = *(const float4*)&bW[n_blk + tx * 4];
#pragma unroll
    for (int i = 0; i < 4; ++i) {
        float4 c;
        c.x = acc[i][0] + bw4.x; c.y = acc[i][1] + bw4.y;
        c.z = acc[i][2] + bw4.z; c.w = acc[i][3] + bw4.w;
        *(float4*)&g_xw[(size_t)(m_blk + ty * 4 + i) * HH + n_blk + tx * 4] = c;
    }
}

// =====================================================================
// Kernel 2: persistent scan.
// 128 CTAs = 4 b-tiles (16 batch each) x 32 n-tiles (32 cols of U each).
// U slice (32x1024 fp32, row stride 1028 for bank-conflict-free float4
// reads) lives in SMEM for all 512 steps. Per step:
//   Phase A: h3s[bi][k] = tanh(xw[b,t,k] + state[b,k]) into smem
//            (nt==0 CTA also streams h3 to out1 / out2)
//   Phase B: t_next[b, n] = bU[n] + sum_k h3s[b][k] * Us[n][k]
//   one grid barrier.
// =====================================================================
#define SCAN_CTAS 128
#define U_STRIDE 1028   // 1028 % 32 == 4 -> conflict-free float4 col reads
#define SMEM_SCAN ((32 * U_STRIDE + 16 * 1024) * 4)   // 197120 bytes

__global__ __launch_bounds__(256, 1) void scan_kernel(
    const float* __restrict__ U, const float* __restrict__ bU,
    float* __restrict__ out1, float* __restrict__ out2)
{
    extern __shared__ float smem[];
    float* Us  = smem;                    // [32][U_STRIDE]
    float* h3s = smem + 32 * U_STRIDE;    // [16][1024]

    const int tid = threadIdx.x;
    const int bt = blockIdx.x >> 5;       // 0..3
    const int nt = blockIdx.x & 31;       // 0..31
    const int b0 = bt * 16;
    const int n0 = nt * 32;

    // load U slice into SMEM once (rows n0..n0+31)
    for (int idx = tid; idx < 32 * 256; idx += 256) {
        int r = idx >> 8, k4 = idx & 255;
        float4 u = *(const float4*)&U[(size_t)(n0 + r) * HH + k4 * 4];
        *(float4*)&Us[r * U_STRIDE + k4 * 4] = u;
    }

    const int n_loc = tid & 31;           // 0..31 (column within slice)
    const int bg    = tid >> 5;           // 0..7
    const int bi0   = bg * 2;             // thread owns batch rows bi0, bi0+1
    const float bu  = bU[n0 + n_loc];

    // zero initial state (t0 = 0); disjoint coverage across CTAs/threads
    g_state[0][(size_t)(b0 + bi0)     * HH + n0 + n_loc] = 0.0f;
    g_state[0][(size_t)(b0 + bi0 + 1) * HH + n0 + n_loc] = 0.0f;
    __threadfence();
    grid_sync(SCAN_CTAS);

    for (int t = 0; t < TT; ++t) {
        const float* scur  = g_state[t & 1];
        float*       snext = g_state[(t & 1) ^ 1];

        // ---- Phase A: h3 = tanh(xw_t + state) ----
        for (int e = tid; e < 16 * 256; e += 256) {
            int bi = e >> 8, k4 = e & 255;
            int b = b0 + bi;
            size_t off = ((size_t)b * TT + t) * HH + k4 * 4;
            float4 xv = *(const float4*)&g_xw[off];
            float4 sv = *(const float4*)&scur[(size_t)b * HH + k4 * 4];
            float4 h;
            h.x = fast_tanh(xv.x + sv.x);
            h.y = fast_tanh(xv.y + sv.y);
            h.z = fast_tanh(xv.z + sv.z);
            h.w = fast_tanh(xv.w + sv.w);
            *(float4*)&h3s[bi * 1024 + k4 * 4] = h;
            if (nt == 0) {
                *(float4*)&out1[off] = h;
                if (t == TT - 1)
                    *(float4*)&out2[(size_t)b * HH + k4 * 4] = h;
            }
        }
        __syncthreads();

        // ---- Phase B: t_next = h3 @ U^T + bU  (this CTA's 16x32 tile) ----
        float acc0 = bu, acc1 = bu;
        const float* urow = &Us[n_loc * U_STRIDE];
        const float* har  = &h3s[bi0 * 1024];
        const float* hbr  = &h3s[(bi0 + 1) * 1024];
#pragma unroll 4
        for (int k4 = 0; k4 < 256; ++k4) {
            float4 u  = *(const float4*)&urow[k4 * 4];
            float4 ha = *(const float4*)&har[k4 * 4];
            float4 hb = *(const float4*)&hbr[k4 * 4];
            acc0 = fmaf(u.x, ha.x, acc0);
            acc0 = fmaf(u.y, ha.y, acc0);
            acc0 = fmaf(u.z, ha.z, acc0);
            acc0 = fmaf(u.w, ha.w, acc0);
            acc1 = fmaf(u.x, hb.x, acc1);
            acc1 = fmaf(u.y, hb.y, acc1);
            acc1 = fmaf(u.z, hb.z, acc1);
            acc1 = fmaf(u.w, hb.w, acc1);
        }
        snext[(size_t)(b0 + bi0)     * HH + n0 + n_loc] = acc0;
        snext[(size_t)(b0 + bi0 + 1) * HH + n0 + n_loc] = acc1;
        __threadfence();
        grid_sync(SCAN_CTAS);
    }
}

// =====================================================================
// launch
// =====================================================================
extern "C" void kernel_launch(void* const* d_in, const int* in_sizes, int n_in,
                              void* d_out, int out_size)
{
    const float* x  = (const float*)d_in[0];
    const float* W  = (const float*)d_in[1];
    const float* bW = (const float*)d_in[2];
    const float* U  = (const float*)d_in[3];
    const float* bU = (const float*)d_in[4];

    float* out1 = (float*)d_out;
    float* out2 = out1 + (size_t)BB * TT * HH;

    cudaFuncSetAttribute(scan_kernel,
                         cudaFuncAttributeMaxDynamicSharedMemorySize, SMEM_SCAN);

    dim3 g1(HH / BN, (BB * TT) / BM);   // (16, 512)
    gemm1_kernel<<<g1, 256>>>(x, W, bW);
    scan_kernel<<<SCAN_CTAS, 256, SMEM_SCAN>>>(U, bU, out1, out2);
}